// round 16
// baseline (speedup 1.0000x reference)
#include <cuda_runtime.h>
#include <math.h>

#define H 128
#define B 512
#define RANKS 3
#define POOL_BLOCKS_X 512
#define POOL_THREADS 256
#define POOL_WARPS_PER_RANK (POOL_BLOCKS_X * POOL_THREADS / 32)

// ---------------- scratch (no allocations allowed) ----------------
__device__ float g_sum [RANKS][B * H];
__device__ float g_gsum[RANKS][B * H];
__device__ float g_max [RANKS][B * H];
__device__ float g_cnt [RANKS][B];
__device__ float g_state[B][3 * H];

__device__ __forceinline__ void atomicMaxF(float* addr, float v) {
    if (v >= 0.f) atomicMax((int*)addr, __float_as_int(v));
    else          atomicMin((unsigned int*)addr, __float_as_uint(v));
}

// ---------------- init: reset accumulators every replay ----------------
__global__ void init_kernel() {
    int i = blockIdx.x * blockDim.x + threadIdx.x;
    int stride = gridDim.x * blockDim.x;
    int tot = RANKS * B * H;
    for (int idx = i; idx < tot; idx += stride) {
        int r = idx / (B * H);
        int o = idx - r * (B * H);
        g_sum[r][o]  = 0.f;
        g_gsum[r][o] = 0.f;
        g_max[r][o]  = -INFINITY;
    }
    if (i < RANKS * B) g_cnt[i / B][i % B] = 0.f;
}

// ---------------- stage 1: fused gated multi-agg pooling (all 3 ranks) ----
__global__ void __launch_bounds__(POOL_THREADS)
pool_kernel(const float* __restrict__ h0, const float* __restrict__ h1,
            const float* __restrict__ h2,
            const int* __restrict__ bb0, const int* __restrict__ bb1,
            const int* __restrict__ bb2,
            const float* __restrict__ Wg0, const float* __restrict__ Wg1,
            const float* __restrict__ Wg2,
            const float* __restrict__ bgp0, const float* __restrict__ bgp1,
            const float* __restrict__ bgp2,
            int N0, int N1, int N2) {
    int rank = blockIdx.y;
    const float* __restrict__ h  = (rank == 0) ? h0  : (rank == 1) ? h1  : h2;
    const int*   __restrict__ b  = (rank == 0) ? bb0 : (rank == 1) ? bb1 : bb2;
    const float* __restrict__ Wg = (rank == 0) ? Wg0 : (rank == 1) ? Wg1 : Wg2;
    const float* __restrict__ bg = (rank == 0) ? bgp0 : (rank == 1) ? bgp1 : bgp2;
    int N = (rank == 0) ? N0 : (rank == 1) ? N1 : N2;

    int npw = (N + POOL_WARPS_PER_RANK - 1) / POOL_WARPS_PER_RANK;
    int gwid = (blockIdx.x * blockDim.x + threadIdx.x) >> 5;
    int lane = threadIdx.x & 31;
    int start = gwid * npw;
    if (start >= N) return;
    int end = min(N, start + npw);

    float4 wg = reinterpret_cast<const float4*>(Wg)[lane];
    float bgv = bg[0];

    float* __restrict__ sums  = g_sum[rank];
    float* __restrict__ gsums = g_gsum[rank];
    float* __restrict__ maxs  = g_max[rank];
    float* __restrict__ cnts  = g_cnt[rank];

    const float4* __restrict__ h4 = reinterpret_cast<const float4*>(h);

    int cur = b[start];
    float4 s4  = make_float4(0.f, 0.f, 0.f, 0.f);
    float4 gs4 = make_float4(0.f, 0.f, 0.f, 0.f);
    float4 m4  = make_float4(-INFINITY, -INFINITY, -INFINITY, -INFINITY);
    float  c   = 0.f;

    auto flush = [&]() {
        int base = cur * H + (lane << 2);
        atomicAdd(&sums[base + 0], s4.x);
        atomicAdd(&sums[base + 1], s4.y);
        atomicAdd(&sums[base + 2], s4.z);
        atomicAdd(&sums[base + 3], s4.w);
        atomicAdd(&gsums[base + 0], gs4.x);
        atomicAdd(&gsums[base + 1], gs4.y);
        atomicAdd(&gsums[base + 2], gs4.z);
        atomicAdd(&gsums[base + 3], gs4.w);
        atomicMaxF(&maxs[base + 0], m4.x);
        atomicMaxF(&maxs[base + 1], m4.y);
        atomicMaxF(&maxs[base + 2], m4.z);
        atomicMaxF(&maxs[base + 3], m4.w);
        if (lane == 0) atomicAdd(&cnts[cur], c);
    };

    auto acc1 = [&](const float4& v, float g) {
        s4.x += v.x;  s4.y += v.y;  s4.z += v.z;  s4.w += v.w;
        m4.x = fmaxf(m4.x, v.x);  m4.y = fmaxf(m4.y, v.y);
        m4.z = fmaxf(m4.z, v.z);  m4.w = fmaxf(m4.w, v.w);
        gs4.x += g * v.x;  gs4.y += g * v.y;
        gs4.z += g * v.z;  gs4.w += g * v.w;
        c += 1.f;
    };

    int n = start;
    while (n < end) {
        if (n + 8 <= end) {
            int same = 1;
            #pragma unroll
            for (int u = 0; u < 8; ++u) same &= (b[n + u] == cur);
            if (same) {
                float4 v[8];
                #pragma unroll
                for (int u = 0; u < 8; ++u)
                    v[u] = __ldcs(&h4[(n + u) * 32 + lane]);
                float p[8];
                #pragma unroll
                for (int u = 0; u < 8; ++u)
                    p[u] = v[u].x * wg.x + v[u].y * wg.y + v[u].z * wg.z + v[u].w * wg.w;
                #pragma unroll
                for (int o = 16; o; o >>= 1) {
                    #pragma unroll
                    for (int u = 0; u < 8; ++u)
                        p[u] += __shfl_xor_sync(0xffffffffu, p[u], o);
                }
                #pragma unroll
                for (int u = 0; u < 8; ++u) {
                    float g = 1.f / (1.f + __expf(-(p[u] + bgv)));
                    acc1(v[u], g);
                }
                n += 8;
                continue;
            }
        }
        int seg = b[n];
        float4 v = __ldcs(&h4[n * 32 + lane]);
        if (seg != cur) {
            flush();
            s4  = make_float4(0.f, 0.f, 0.f, 0.f);
            gs4 = make_float4(0.f, 0.f, 0.f, 0.f);
            m4  = make_float4(-INFINITY, -INFINITY, -INFINITY, -INFINITY);
            c   = 0.f;
            cur = seg;
        }
        float p = v.x * wg.x + v.y * wg.y + v.z * wg.z + v.w * wg.w;
        #pragma unroll
        for (int o = 16; o; o >>= 1) p += __shfl_xor_sync(0xffffffffu, p, o);
        float g = 1.f / (1.f + __expf(-(p + bgv)));
        acc1(v, g);
        ++n;
    }
    flush();
}

// ---------------- stage 2: projection, no split-K -------------------------
// grid (B/8, 3) = 192 blocks, 256 threads. j = tid&127 (output column),
// half = tid>>7 picks 4 of the 8 staged segments. Each thread runs the FULL
// K=512 in registers: 8 weight scalars per iter (coalesced, MLP=8; both
// halves read identical addresses -> L1 dedup), a[s][k] smem reads are
// warp-uniform broadcasts. No partials, no extra syncs, 16KB smem.
__global__ void __launch_bounds__(256)
proj_kernel(const float* __restrict__ Wp0, const float* __restrict__ bp0,
            const float* __restrict__ Wp1, const float* __restrict__ bp1,
            const float* __restrict__ Wp2, const float* __restrict__ bp2) {
    int rank = blockIdx.y;
    const float* Wp = (rank == 0) ? Wp0 : (rank == 1) ? Wp1 : Wp2;
    const float* bp = (rank == 0) ? bp0 : (rank == 1) ? bp1 : bp2;
    int seg0 = blockIdx.x * 8;
    int tid = threadIdx.x;

    __shared__ float a[8][512];
    __shared__ float csh[8];

    const float* __restrict__ sums  = g_sum[rank];
    const float* __restrict__ gsums = g_gsum[rank];
    const float* __restrict__ maxs  = g_max[rank];

    if (tid < 8) csh[tid] = g_cnt[rank][seg0 + tid];
    __syncthreads();

    for (int idx = tid; idx < 8 * 512; idx += 256) {
        int s = idx >> 9;
        int k = idx & 511;
        int seg = seg0 + s;
        float v;
        if (k < 128)      v = sums[seg * H + k];
        else if (k < 256) v = sums[seg * H + (k - 128)] / fmaxf(csh[s], 1.f);
        else if (k < 384) v = (csh[s] > 0.f) ? maxs[seg * H + (k - 256)] : 0.f;
        else              v = gsums[seg * H + (k - 384)];
        a[s][k] = v;
    }
    __syncthreads();

    int j = tid & 127;
    int half = tid >> 7;
    int sbase = half * 4;

    float r[4] = {0.f, 0.f, 0.f, 0.f};
    const float* W = Wp + j;

    for (int kb = 0; kb < 512; kb += 8) {
        float w[8];
        #pragma unroll
        for (int u = 0; u < 8; ++u) w[u] = W[(kb + u) * H];
        #pragma unroll
        for (int s4 = 0; s4 < 4; ++s4) {
            float4 aL = *reinterpret_cast<const float4*>(&a[sbase + s4][kb]);
            float4 aH = *reinterpret_cast<const float4*>(&a[sbase + s4][kb + 4]);
            r[s4] += aL.x * w[0] + aL.y * w[1] + aL.z * w[2] + aL.w * w[3]
                   + aH.x * w[4] + aH.y * w[5] + aH.z * w[6] + aH.w * w[7];
        }
    }

    float bj = bp[j];
    #pragma unroll
    for (int s4 = 0; s4 < 4; ++s4)
        g_state[seg0 + sbase + s4][rank * H + j] = r[s4] + bj;
}

// ---------------- stage 3: LN + SiLU + MLP + dot -> out (fused) -----------
// grid B/2 = 256 blocks, 128 threads, 2 segments/block. j = tid.
__global__ void __launch_bounds__(128)
final_kernel(const float* __restrict__ gamma, const float* __restrict__ beta,
             const float* __restrict__ W1,    const float* __restrict__ b1f,
             const float* __restrict__ W2,    const float* __restrict__ b2f,
             float* __restrict__ out) {
    int seg0 = blockIdx.x * 2;
    int tid = threadIdx.x;
    int wid = tid >> 5;
    int lane = tid & 31;

    __shared__ float a[2][384];
    __shared__ float red[2][4];

    for (int idx = tid; idx < 2 * 384; idx += 128) {
        int s = idx / 384;
        int k = idx - s * 384;
        a[s][k] = g_state[seg0 + s][k];
    }
    __syncthreads();

    // LN + SiLU: warp 0 -> row 0, warp 1 -> row 1
    if (wid < 2) {
        int s = wid;
        float vals[12];
        float ps = 0.f;
        #pragma unroll
        for (int kk = 0; kk < 12; ++kk) {
            vals[kk] = a[s][lane + kk * 32];
            ps += vals[kk];
        }
        #pragma unroll
        for (int o = 16; o; o >>= 1) ps += __shfl_xor_sync(0xffffffffu, ps, o);
        float mu = ps * (1.f / 384.f);
        float pv = 0.f;
        #pragma unroll
        for (int kk = 0; kk < 12; ++kk) {
            float d = vals[kk] - mu;
            pv += d * d;
        }
        #pragma unroll
        for (int o = 16; o; o >>= 1) pv += __shfl_xor_sync(0xffffffffu, pv, o);
        float rstd = rsqrtf(pv * (1.f / 384.f) + 1e-5f);
        #pragma unroll
        for (int kk = 0; kk < 12; ++kk) {
            int k = lane + kk * 32;
            float xn = (vals[kk] - mu) * rstd * gamma[k] + beta[k];
            a[s][k] = xn / (1.f + __expf(-xn));   // silu
        }
    }
    __syncthreads();

    // MLP 384->128, full K per thread
    float r0 = 0.f, r1 = 0.f;
    const float* W = W1 + tid;
    for (int kb = 0; kb < 384; kb += 8) {
        float w[8];
        #pragma unroll
        for (int u = 0; u < 8; ++u) w[u] = W[(kb + u) * H];
        float4 aL0 = *reinterpret_cast<const float4*>(&a[0][kb]);
        float4 aH0 = *reinterpret_cast<const float4*>(&a[0][kb + 4]);
        float4 aL1 = *reinterpret_cast<const float4*>(&a[1][kb]);
        float4 aH1 = *reinterpret_cast<const float4*>(&a[1][kb + 4]);
        r0 += aL0.x * w[0] + aL0.y * w[1] + aL0.z * w[2] + aL0.w * w[3]
            + aH0.x * w[4] + aH0.y * w[5] + aH0.z * w[6] + aH0.w * w[7];
        r1 += aL1.x * w[0] + aL1.y * w[1] + aL1.z * w[2] + aL1.w * w[3]
            + aH1.x * w[4] + aH1.y * w[5] + aH1.z * w[6] + aH1.w * w[7];
    }

    float b1j = b1f[tid];
    float w2j = W2[tid];
    float x0 = r0 + b1j;
    float x1 = r1 + b1j;
    x0 = x0 / (1.f + __expf(-x0));
    x1 = x1 / (1.f + __expf(-x1));
    float v0 = x0 * w2j;
    float v1 = x1 * w2j;

    #pragma unroll
    for (int o = 16; o; o >>= 1) {
        v0 += __shfl_xor_sync(0xffffffffu, v0, o);
        v1 += __shfl_xor_sync(0xffffffffu, v1, o);
    }
    if (lane == 0) {
        red[0][wid] = v0;
        red[1][wid] = v1;
    }
    __syncthreads();
    if (tid < 2) {
        float p = red[tid][0] + red[tid][1] + red[tid][2] + red[tid][3];
        out[seg0 + tid] = p + b2f[0];
    }
}

// ---------------- launch ----------------
extern "C" void kernel_launch(void* const* d_in, const int* in_sizes, int n_in,
                              void* d_out, int out_size) {
    const float* h0  = (const float*)d_in[0];
    const float* h1  = (const float*)d_in[1];
    const float* h2  = (const float*)d_in[2];
    const int*   b0  = (const int*)d_in[3];
    const int*   b1  = (const int*)d_in[4];
    const int*   b2  = (const int*)d_in[5];
    const float* Wg0 = (const float*)d_in[6];
    const float* bg0 = (const float*)d_in[7];
    const float* Wg1 = (const float*)d_in[8];
    const float* bg1 = (const float*)d_in[9];
    const float* Wg2 = (const float*)d_in[10];
    const float* bg2 = (const float*)d_in[11];
    const float* Wp0 = (const float*)d_in[12];
    const float* bp0 = (const float*)d_in[13];
    const float* Wp1 = (const float*)d_in[14];
    const float* bp1 = (const float*)d_in[15];
    const float* Wp2 = (const float*)d_in[16];
    const float* bp2 = (const float*)d_in[17];
    const float* gamma = (const float*)d_in[18];
    const float* beta  = (const float*)d_in[19];
    const float* W1  = (const float*)d_in[20];
    const float* b1f = (const float*)d_in[21];
    const float* W2  = (const float*)d_in[22];
    const float* b2f = (const float*)d_in[23];

    int N0 = in_sizes[3];
    int N1 = in_sizes[4];
    int N2 = in_sizes[5];

    init_kernel<<<384, 256>>>();

    dim3 gpool(POOL_BLOCKS_X, RANKS);
    pool_kernel<<<gpool, POOL_THREADS>>>(h0, h1, h2, b0, b1, b2,
                                         Wg0, Wg1, Wg2, bg0, bg1, bg2,
                                         N0, N1, N2);

    dim3 gp(B / 8, RANKS);
    proj_kernel<<<gp, 256>>>(Wp0, bp0, Wp1, bp1, Wp2, bp2);

    final_kernel<<<B / 2, 128>>>(gamma, beta, W1, b1f, W2, b2f, (float*)d_out);
}